// round 8
// baseline (speedup 1.0000x reference)
#include <cuda_runtime.h>
#include <cstdint>

// Problem constants
#define Bn 4
#define Cn 32
#define Ln 256
#define Mn 256
#define Fn 8
#define Nn 64
#define FC (Fn * Cn)          // 256
#define LM (Ln * Mn)          // 65536
#define IMAG_OFF ((size_t)Bn * Fn * LM)  // 2,097,152
#define CB 8                  // c-batch size (front-batched loads)

union U64 {
    unsigned long long u;
    float2 f;
};

__device__ __forceinline__ unsigned long long ffma2(unsigned long long a,
                                                    unsigned long long b,
                                                    unsigned long long c) {
    unsigned long long d;
    asm("fma.rn.f32x2 %0, %1, %2, %3;" : "=l"(d) : "l"(a), "l"(b), "l"(c));
    return d;
}

// ---------------------------------------------------------------------------
// Grid: B*L = 1024 blocks, 128 threads. Block = one (b, l).
// Thread t: m-pair t (2 consecutive m), all 8 f.
// c-loop in 4 batches of 8 front-batched LDG.64; 7 blocks/SM = ONE full wave.
// ---------------------------------------------------------------------------
__global__ __launch_bounds__(128, 7) void sphere_v8_kernel(
    const float* __restrict__ xr,
    const float* __restrict__ xi,
    const float* __restrict__ wr,
    const float* __restrict__ wi,
    float* __restrict__ out) {
    __shared__ ulonglong2 s2[FC];   // 4 KB: { {wr,wr}, {wi,wi} } per (f,c)

    int bid = blockIdx.x;
    int b = bid >> 8;
    int l = bid & (Ln - 1);
    int tid = threadIdx.x;

    // --- interpolate this l's weights into shared ---
    {
        float t = (float)l * (63.0f / 255.0f);
        int lo = (int)t;
        if (lo > Nn - 2) lo = Nn - 2;
        float fr = t - (float)lo;
        float om = 1.0f - fr;
#pragma unroll
        for (int j = 0; j < 2; ++j) {
            int k = tid + j * 128;
            const float* pwr = wr + k * Nn + lo;
            const float* pwi = wi + k * Nn + lo;
            float vr = pwr[0] * om + pwr[1] * fr;
            float vi = pwi[0] * om + pwi[1] * fr;
            U64 ur, ui;
            ur.f = make_float2(vr, vr);
            ui.f = make_float2(vi, vi);
            s2[k] = make_ulonglong2(ur.u, ui.u);
        }
    }
    __syncthreads();

    int m0 = tid * 2;
    const unsigned long long* pr = reinterpret_cast<const unsigned long long*>(
        xr + (size_t)b * Cn * LM + (size_t)l * Mn + m0);
    const unsigned long long* pi = reinterpret_cast<const unsigned long long*>(
        xi + (size_t)b * Cn * LM + (size_t)l * Mn + m0);
    const int step = LM / 2;   // u64 stride per c (byte offset fits imm24)

    unsigned long long ar[Fn], ai[Fn];
#pragma unroll
    for (int f = 0; f < Fn; ++f) { ar[f] = 0ull; ai[f] = 0ull; }

    const unsigned long long SMSK = 0x8000000080000000ULL;

#pragma unroll
    for (int cb = 0; cb < Cn; cb += CB) {
        // ---- front-batched loads: 16 LDG.64 with constant offsets ----
        unsigned long long xrv[CB], xiv[CB];
#pragma unroll
        for (int j = 0; j < CB; ++j) {
            xrv[j] = __ldg(pr + j * step);
            xiv[j] = __ldg(pi + j * step);
        }
        pr += CB * step;
        pi += CB * step;

        // ---- compute over the batch ----
#pragma unroll
        for (int j = 0; j < CB; ++j) {
            int c = cb + j;
            unsigned long long xrc = xrv[j];
            unsigned long long xic = xiv[j];
            unsigned long long nxi = xic ^ SMSK;
#pragma unroll
            for (int f = 0; f < Fn; ++f) {
                ulonglong2 w = s2[f * Cn + c];   // broadcast LDS.128
                ar[f] = ffma2(w.x, xrc, ar[f]);
                ar[f] = ffma2(w.y, nxi, ar[f]);
                ai[f] = ffma2(w.x, xic, ai[f]);
                ai[f] = ffma2(w.y, xrc, ai[f]);
            }
        }
    }

    float sc = sqrtf(1.0f + (float)l) * (1.0f / 32.0f);
    float* o_real = out + (size_t)b * Fn * LM + (size_t)l * Mn + m0;
    float* o_imag = o_real + IMAG_OFF;

#pragma unroll
    for (int f = 0; f < Fn; ++f) {
        U64 u;
        u.u = ar[f];
        float2 vr2;
        vr2.x = fmaxf(u.f.x * sc, 0.0f);
        vr2.y = fmaxf(u.f.y * sc, 0.0f);
        *reinterpret_cast<float2*>(o_real + (size_t)f * LM) = vr2;

        u.u = ai[f];
        float2 vi2;
        vi2.x = u.f.x * sc;
        vi2.y = u.f.y * sc;
        *reinterpret_cast<float2*>(o_imag + (size_t)f * LM) = vi2;
    }
}

extern "C" void kernel_launch(void* const* d_in, const int* in_sizes, int n_in,
                              void* d_out, int out_size) {
    const float* x_real = (const float*)d_in[0];
    const float* x_imag = (const float*)d_in[1];
    const float* w_real = (const float*)d_in[2];
    const float* w_imag = (const float*)d_in[3];
    float* out = (float*)d_out;

    sphere_v8_kernel<<<Bn * Ln, 128>>>(x_real, x_imag, w_real, w_imag, out);
}